// round 14
// baseline (speedup 1.0000x reference)
#include <cuda_runtime.h>
#include <cuda_fp16.h>
#include <cstdint>

// Problem constants (from reference): N=50000, DIM=64, HEADS=4, E=800000.
#define MAXN 50000
#define MAXE 800000
#define MAXET (MAXE + MAXN)
#define HC 256   // HEADS * DIM

// ---------------- scratch (static device globals; no allocation) ----------------
__device__ __align__(16) float g_xf[MAXN * HC];       // [N, H, C] = x @ W  (fp32)
__device__ __align__(16) __half g_wh[64 * 256];       // fp16 copy of W
__device__ __align__(16) float g_asrc[MAXN * 4];      // [N, H]
__device__ __align__(16) float g_adst[MAXN * 4];      // [N, H]
__device__ int    g_deg[MAXN];
__device__ int    g_off[MAXN + 1];
__device__ int    g_flag[64];                         // lookback: 0=unready else agg+1
__device__ __align__(8) int g_rank[MAXET];            // within-dst rank of each edge
__device__ float4 g_pack[MAXET];                      // CSR rec: {src:int, exp01:h2, exp23:h2, pad}
__device__ int    g_is64;                             // 1 if edge buffer is int64

// ---------------- detect int64/int32 + init counters/flags + W->fp16 (merged) ----------------
__global__ void detect_init_wh_kernel(const int* __restrict__ e32,
                                      const float* __restrict__ W, int N) {
    int i = blockIdx.x * blockDim.x + threadIdx.x;
    if (i < N) g_deg[i] = 0;
    if (i < 64) g_flag[i] = 0;
    if (blockIdx.x == 0) {
        __shared__ int s_any;
        if (threadIdx.x == 0) s_any = 0;
        __syncthreads();
        int any = 0;
        for (int k = threadIdx.x; k < 2048; k += blockDim.x)
            any |= e32[2 * k + 1];
        if (any) atomicOr(&s_any, 1);
        __syncthreads();
        if (threadIdx.x == 0) g_is64 = s_any ? 0 : 1;
    } else if (blockIdx.x <= 16) {
        int j = (blockIdx.x - 1) * 256 + threadIdx.x;   // 0..4095, 4 floats each
        float4 v = *(const float4*)&W[j * 4];
        *(__half2*)&g_wh[j * 4]     = __floats2half2_rn(v.x, v.y);
        *(__half2*)&g_wh[j * 4 + 2] = __floats2half2_rn(v.z, v.w);
    }
}

// ---------------- degree role: 512 threads, 2 edges per thread ----------------
__device__ __forceinline__ void degree_role(const int* __restrict__ e32,
                                            int N, int E, int blk) {
    int p = blk * 512 + threadIdx.x;
    int ET = E + N;
    int e0 = 2 * p, e1 = 2 * p + 1;
    if (e0 >= ET) return;
    bool has1 = (e1 < ET);
    int d0, d1 = 0;
    if (e1 < E) {
        if (g_is64) {
            int4 v = *(const int4*)&e32[2 * E + 4 * p];
            d0 = v.x; d1 = v.z;
        } else {
            int2 v = *(const int2*)&e32[E + 2 * p];
            d0 = v.x; d1 = v.y;
        }
    } else if (e0 >= E) {
        d0 = e0 - E;
        d1 = e1 - E;
    } else {
        d0 = (e0 < E) ? (g_is64 ? e32[2 * E + 2 * e0] : e32[E + e0]) : e0 - E;
        d1 = has1 ? ((e1 < E) ? (g_is64 ? e32[2 * E + 2 * e1] : e32[E + e1]) : e1 - E) : 0;
    }
    int r0 = atomicAdd(&g_deg[d0], 1);
    if (has1) {
        int r1 = atomicAdd(&g_deg[d1], 1);
        *(int2*)&g_rank[e0] = make_int2(r0, r1);
    } else {
        g_rank[e0] = r0;
    }
}

// ---------------- fused + interleaved: degree blocks + HMMA GEMM blocks ----------------
__global__ void __launch_bounds__(512, 2) gemm_degree_kernel(
        const float* __restrict__ X,
        const float* __restrict__ att_src,
        const float* __restrict__ att_dst,
        const int* __restrict__ e32,
        int N, int E, int degBlocks, int gemmBlocks) {
    __shared__ __half sA[64][72];
    __shared__ __half sB[64][264];

    int b = blockIdx.x;
    int mn = degBlocks < gemmBlocks ? degBlocks : gemmBlocks;
    int nI = 2 * mn;
    bool isDeg;
    int idx;
    if (b < nI) { isDeg = (b & 1) == 0; idx = b >> 1; }
    else        { isDeg = degBlocks > gemmBlocks; idx = mn + (b - nI); }

    if (isDeg) {
        degree_role(e32, N, E, idx);
        return;
    }
    int row0 = idx * 64;
    int t = threadIdx.x;

    #pragma unroll
    for (int i = t; i < 2048; i += 512) {
        int idx2 = i * 8;
        int k = idx2 >> 8, n = idx2 & 255;
        *(uint4*)&sB[k][n] = *(const uint4*)&g_wh[idx2];
    }
    #pragma unroll
    for (int i = t; i < 1024; i += 512) {
        int idx2 = i * 4;
        int r = idx2 >> 6, k = idx2 & 63;
        int row = row0 + r;
        float4 v = (row < N) ? *(const float4*)&X[row * 64 + k]
                             : make_float4(0.f, 0.f, 0.f, 0.f);
        *(__half2*)&sA[r][k]     = __floats2half2_rn(v.x, v.y);
        *(__half2*)&sA[r][k + 2] = __floats2half2_rn(v.z, v.w);
    }
    __syncthreads();

    int w = t >> 5, lane = t & 31;
    int wr = (w & 3) * 16;
    int h  = w >> 2;
    int wc = h * 64;
    int m8 = lane >> 3, i8 = lane & 7;
    int rg = (m8 & 1) * 8 + i8;
    int cg = (m8 >> 1) * 8;

    float acc[8][4] = {};

    #pragma unroll
    for (int ki = 0; ki < 4; ki++) {
        uint32_t a0, a1, a2, a3;
        {
            uint32_t addr = (uint32_t)__cvta_generic_to_shared(
                &sA[wr + rg][ki * 16 + cg]);
            asm volatile("ldmatrix.sync.aligned.m8n8.x4.shared.b16 {%0,%1,%2,%3}, [%4];"
                         : "=r"(a0), "=r"(a1), "=r"(a2), "=r"(a3) : "r"(addr));
        }
        #pragma unroll
        for (int nj = 0; nj < 4; nj++) {
            uint32_t b0, b1, b2, b3;
            uint32_t addr = (uint32_t)__cvta_generic_to_shared(
                &sB[ki * 16 + rg][wc + nj * 16 + cg]);
            asm volatile("ldmatrix.sync.aligned.m8n8.x4.trans.shared.b16 {%0,%1,%2,%3}, [%4];"
                         : "=r"(b0), "=r"(b1), "=r"(b2), "=r"(b3) : "r"(addr));
            asm volatile(
                "mma.sync.aligned.m16n8k16.row.col.f32.f16.f16.f32 "
                "{%0,%1,%2,%3}, {%4,%5,%6,%7}, {%8,%9}, {%0,%1,%2,%3};"
                : "+f"(acc[nj * 2][0]), "+f"(acc[nj * 2][1]),
                  "+f"(acc[nj * 2][2]), "+f"(acc[nj * 2][3])
                : "r"(a0), "r"(a1), "r"(a2), "r"(a3), "r"(b0), "r"(b1));
            asm volatile(
                "mma.sync.aligned.m16n8k16.row.col.f32.f16.f16.f32 "
                "{%0,%1,%2,%3}, {%4,%5,%6,%7}, {%8,%9}, {%0,%1,%2,%3};"
                : "+f"(acc[nj * 2 + 1][0]), "+f"(acc[nj * 2 + 1][1]),
                  "+f"(acc[nj * 2 + 1][2]), "+f"(acc[nj * 2 + 1][3])
                : "r"(a0), "r"(a1), "r"(a2), "r"(a3), "r"(b2), "r"(b3));
        }
    }

    int rrow = lane >> 2, rcol = (lane & 3) * 2;
    int row = row0 + wr + rrow;
    float ps = 0.f, pd = 0.f, ps8 = 0.f, pd8 = 0.f;
    #pragma unroll
    for (int ni = 0; ni < 8; ni++) {
        int col = wc + ni * 8 + rcol;
        if (row < N)
            *(float2*)&g_xf[row * HC + col] = make_float2(acc[ni][0], acc[ni][1]);
        if (row + 8 < N)
            *(float2*)&g_xf[(row + 8) * HC + col] = make_float2(acc[ni][2], acc[ni][3]);
        float2 as2 = *(const float2*)&att_src[col];
        float2 ad2 = *(const float2*)&att_dst[col];
        ps  += acc[ni][0] * as2.x + acc[ni][1] * as2.y;
        pd  += acc[ni][0] * ad2.x + acc[ni][1] * ad2.y;
        ps8 += acc[ni][2] * as2.x + acc[ni][3] * as2.y;
        pd8 += acc[ni][2] * ad2.x + acc[ni][3] * ad2.y;
    }
    #pragma unroll
    for (int o = 1; o < 4; o <<= 1) {
        ps  += __shfl_xor_sync(0xffffffffu, ps,  o);
        pd  += __shfl_xor_sync(0xffffffffu, pd,  o);
        ps8 += __shfl_xor_sync(0xffffffffu, ps8, o);
        pd8 += __shfl_xor_sync(0xffffffffu, pd8, o);
    }
    if ((lane & 3) == 0) {
        if (row < N) {
            g_asrc[row * 4 + h] = ps;
            g_adst[row * 4 + h] = pd;
        }
        if (row + 8 < N) {
            g_asrc[(row + 8) * 4 + h] = ps8;
            g_adst[(row + 8) * 4 + h] = pd8;
        }
    }
}

// ---------------- single-pass decoupled-lookback scan: deg -> exclusive g_off ----------------
__global__ void scan_lookback(int N, int ET, int nb) {
    __shared__ int wsum[32];
    __shared__ int s_prev;
    int b = blockIdx.x;
    int t = threadIdx.x, lane = t & 31, wid = t >> 5;
    int i = b * 1024 + t;
    int v = (i < N) ? g_deg[i] : 0;
    int x = v;
    #pragma unroll
    for (int o = 1; o < 32; o <<= 1) {
        int y = __shfl_up_sync(0xffffffffu, x, o);
        if (lane >= o) x += y;
    }
    if (lane == 31) wsum[wid] = x;
    if (t == 0) s_prev = 0;
    __syncthreads();
    if (wid == 0) {
        int w = wsum[lane];
        #pragma unroll
        for (int o = 1; o < 32; o <<= 1) {
            int y = __shfl_up_sync(0xffffffffu, w, o);
            if (lane >= o) w += y;
        }
        wsum[lane] = w;
    }
    __syncthreads();
    int agg = wsum[31];
    if (t == 0) atomicExch(&g_flag[b], agg + 1);
    if (t < b) {
        int f;
        do { f = atomicAdd(&g_flag[t], 0); } while (f == 0);
        atomicAdd(&s_prev, f - 1);
    }
    __syncthreads();
    int base = s_prev;
    int ex = (wid ? wsum[wid - 1] : 0) + x - v;
    if (i < N) g_off[i] = base + ex;
    if (b == nb - 1 && t == 0) g_off[N] = ET;
}

// ---------------- edge pass 2: 2 edges per thread; h2exp ----------------
__device__ __forceinline__ float4 make_rec(int s, const float4& as, const float4& ad) {
    float l0 = as.x + ad.x, l1 = as.y + ad.y, l2 = as.z + ad.z, l3 = as.w + ad.w;
    l0 = l0 > 0.f ? l0 : 0.2f * l0;
    l1 = l1 > 0.f ? l1 : 0.2f * l1;
    l2 = l2 > 0.f ? l2 : 0.2f * l2;
    l3 = l3 > 0.f ? l3 : 0.2f * l3;
    __half2 e01 = h2exp(__floats2half2_rn(l0, l1));
    __half2 e23 = h2exp(__floats2half2_rn(l2, l3));
    float4 rec;
    rec.x = __int_as_float(s);
    rec.y = __uint_as_float(*(const unsigned int*)&e01);
    rec.z = __uint_as_float(*(const unsigned int*)&e23);
    rec.w = 0.0f;
    return rec;
}

__global__ void edge_pass2(const int* __restrict__ e32, int N, int E) {
    int p = blockIdx.x * blockDim.x + threadIdx.x;
    int ET = E + N;
    int e0 = 2 * p, e1 = 2 * p + 1;
    if (e0 >= ET) return;
    bool has1 = (e1 < ET);
    int s0, d0, s1 = 0, d1 = 0;
    if (e1 < E) {
        if (g_is64) {
            int4 vs = *(const int4*)&e32[4 * p];
            int4 vd = *(const int4*)&e32[2 * E + 4 * p];
            s0 = vs.x; s1 = vs.z; d0 = vd.x; d1 = vd.z;
        } else {
            int2 vs = *(const int2*)&e32[2 * p];
            int2 vd = *(const int2*)&e32[E + 2 * p];
            s0 = vs.x; s1 = vs.y; d0 = vd.x; d1 = vd.y;
        }
    } else if (e0 >= E) {
        s0 = d0 = e0 - E;
        s1 = d1 = e1 - E;
    } else {
        if (e0 < E) {
            s0 = g_is64 ? e32[2 * e0] : e32[e0];
            d0 = g_is64 ? e32[2 * E + 2 * e0] : e32[E + e0];
        } else { s0 = d0 = e0 - E; }
        if (has1) {
            if (e1 < E) {
                s1 = g_is64 ? e32[2 * e1] : e32[e1];
                d1 = g_is64 ? e32[2 * E + 2 * e1] : e32[E + e1];
            } else { s1 = d1 = e1 - E; }
        }
    }
    float4 as0 = *(const float4*)&g_asrc[s0 * 4];
    float4 ad0 = *(const float4*)&g_adst[d0 * 4];
    float4 as1, ad1;
    if (has1) {
        as1 = *(const float4*)&g_asrc[s1 * 4];
        ad1 = *(const float4*)&g_adst[d1 * 4];
    }
    int2 rk = has1 ? *(const int2*)&g_rank[e0] : make_int2(g_rank[e0], 0);
    float4 rec0 = make_rec(s0, as0, ad0);
    g_pack[g_off[d0] + rk.x] = rec0;
    if (has1) {
        float4 rec1 = make_rec(s1, as1, ad1);
        g_pack[g_off[d1] + rk.y] = rec1;
    }
}

// ---------------- warp-per-dst-node aggregation ----------------
// fp32 gathers (no F2F in hot loop); segsum via striped pre-loop + butterfly.
__global__ void aggregate_kernel(const float* __restrict__ bias,
                                 float* __restrict__ out, int N) {
    int gw = (blockIdx.x * blockDim.x + threadIdx.x) >> 5;
    int lane = threadIdx.x & 31;
    if (gw >= N) return;
    int beg = g_off[gw], end = g_off[gw + 1];

    // striped per-head weight sums
    float sw0 = 0.f, sw1 = 0.f, sw2 = 0.f, sw3 = 0.f;
    for (int j = beg + lane; j < end; j += 32) {
        float4 r = g_pack[j];
        unsigned int u01 = __float_as_uint(r.y);
        unsigned int u23 = __float_as_uint(r.z);
        float2 a = __half22float2(*(const __half2*)&u01);
        float2 c = __half22float2(*(const __half2*)&u23);
        sw0 += a.x; sw1 += a.y; sw2 += c.x; sw3 += c.y;
    }
    #pragma unroll
    for (int o = 16; o > 0; o >>= 1) {
        sw0 += __shfl_xor_sync(0xffffffffu, sw0, o);
        sw1 += __shfl_xor_sync(0xffffffffu, sw1, o);
        sw2 += __shfl_xor_sync(0xffffffffu, sw2, o);
        sw3 += __shfl_xor_sync(0xffffffffu, sw3, o);
    }

    float a00 = 0.f, a01 = 0.f, a10 = 0.f, a11 = 0.f;
    float a20 = 0.f, a21 = 0.f, a30 = 0.f, a31 = 0.f;
    #pragma unroll 2
    for (int j = beg; j < end; j++) {
        float4 rec = g_pack[j];
        int s = __float_as_int(rec.x);
        unsigned int u01 = __float_as_uint(rec.y);
        unsigned int u23 = __float_as_uint(rec.z);
        float2 w01 = __half22float2(*(const __half2*)&u01);
        float2 w23 = __half22float2(*(const __half2*)&u23);
        const float2* xr = (const float2*)(g_xf + s * HC);
        float2 v0 = xr[lane];
        float2 v1 = xr[32 + lane];
        float2 v2 = xr[64 + lane];
        float2 v3 = xr[96 + lane];
        a00 += w01.x * v0.x; a01 += w01.x * v0.y;
        a10 += w01.y * v1.x; a11 += w01.y * v1.y;
        a20 += w23.x * v2.x; a21 += w23.x * v2.y;
        a30 += w23.y * v3.x; a31 += w23.y * v3.y;
    }
    float n0 = 0.25f / (sw0 + 1e-16f);
    float n1 = 0.25f / (sw1 + 1e-16f);
    float n2 = 0.25f / (sw2 + 1e-16f);
    float n3 = 0.25f / (sw3 + 1e-16f);
    int c = 2 * lane;
    float o0 = a00 * n0 + a10 * n1 + a20 * n2 + a30 * n3 + bias[c];
    float o1 = a01 * n0 + a11 * n1 + a21 * n2 + a31 * n3 + bias[c + 1];
    *(float2*)&out[gw * 64 + c] = make_float2(o0, o1);
}

// ---------------- launch ----------------
extern "C" void kernel_launch(void* const* d_in, const int* in_sizes, int n_in,
                              void* d_out, int out_size) {
    const float* meta_x  = (const float*)d_in[0];
    const int*   edge32  = (const int*)d_in[1];
    const float* W       = (const float*)d_in[2];
    const float* att_src = (const float*)d_in[3];
    const float* att_dst = (const float*)d_in[4];
    const float* bias    = (const float*)d_in[5];
    float*       out     = (float*)d_out;

    int N  = in_sizes[0] / 64;
    int E  = in_sizes[1] / 2;
    int ET = E + N;
    int nb = (N + 1023) / 1024;
    int np = (ET + 1) / 2;
    int degBlocks  = (np + 511) / 512;
    int gemmBlocks = (N + 63) / 64;

    detect_init_wh_kernel<<<(N + 255) / 256, 256>>>(edge32, W, N);
    gemm_degree_kernel<<<degBlocks + gemmBlocks, 512>>>(meta_x, att_src, att_dst,
                                                        edge32, N, E, degBlocks, gemmBlocks);
    scan_lookback<<<nb, 1024>>>(N, ET, nb);
    edge_pass2<<<(np + 255) / 256, 256>>>(edge32, N, E);
    aggregate_kernel<<<(N * 32 + 127) / 128, 128>>>(bias, out, N);
}

// round 15
// speedup vs baseline: 1.0414x; 1.0414x over previous
#include <cuda_runtime.h>
#include <cuda_fp16.h>
#include <cstdint>

// Problem constants (from reference): N=50000, DIM=64, HEADS=4, E=800000.
#define MAXN 50000
#define MAXE 800000
#define MAXET (MAXE + MAXN)
#define HC 256   // HEADS * DIM

// g_xh row layout (PERMUTED): for col pair p (0..31) and head h (0..3),
// the half2 (cols 2p,2p+1 of head h) lives at halfs [p*8 + h*2]. One lane's
// uint4 load covers all 4 heads for its col pair.
__device__ __align__(16) __half g_xh[MAXN * HC];
__device__ __align__(16) __half g_wh[64 * 256];       // fp16 copy of W
__device__ __align__(16) float g_asrc[MAXN * 4];      // [N, H]
__device__ __align__(16) float g_adst[MAXN * 4];      // [N, H]
__device__ int    g_deg[MAXN];
__device__ int    g_off[MAXN + 1];
__device__ int    g_flag[64];                         // lookback: 0=unready else agg+1
__device__ __align__(8) int g_rank[MAXET];            // within-dst rank of each edge
__device__ float4 g_pack[MAXET];                      // CSR rec: {src:int, exp01:h2, exp23:h2, pad}
__device__ int    g_is64;                             // 1 if edge buffer is int64

// ---------------- detect int64/int32 + init counters/flags + W->fp16 (merged) ----------------
__global__ void detect_init_wh_kernel(const int* __restrict__ e32,
                                      const float* __restrict__ W, int N) {
    int i = blockIdx.x * blockDim.x + threadIdx.x;
    if (i < N) g_deg[i] = 0;
    if (i < 64) g_flag[i] = 0;
    if (blockIdx.x == 0) {
        __shared__ int s_any;
        if (threadIdx.x == 0) s_any = 0;
        __syncthreads();
        int any = 0;
        for (int k = threadIdx.x; k < 2048; k += blockDim.x)
            any |= e32[2 * k + 1];
        if (any) atomicOr(&s_any, 1);
        __syncthreads();
        if (threadIdx.x == 0) g_is64 = s_any ? 0 : 1;
    } else if (blockIdx.x <= 16) {
        int j = (blockIdx.x - 1) * 256 + threadIdx.x;   // 0..4095, 4 floats each
        float4 v = *(const float4*)&W[j * 4];
        *(__half2*)&g_wh[j * 4]     = __floats2half2_rn(v.x, v.y);
        *(__half2*)&g_wh[j * 4 + 2] = __floats2half2_rn(v.z, v.w);
    }
}

// ---------------- degree role: 512 threads, 2 edges per thread ----------------
__device__ __forceinline__ void degree_role(const int* __restrict__ e32,
                                            int N, int E, int blk) {
    int p = blk * 512 + threadIdx.x;
    int ET = E + N;
    int e0 = 2 * p, e1 = 2 * p + 1;
    if (e0 >= ET) return;
    bool has1 = (e1 < ET);
    int d0, d1 = 0;
    if (e1 < E) {
        if (g_is64) {
            int4 v = *(const int4*)&e32[2 * E + 4 * p];
            d0 = v.x; d1 = v.z;
        } else {
            int2 v = *(const int2*)&e32[E + 2 * p];
            d0 = v.x; d1 = v.y;
        }
    } else if (e0 >= E) {
        d0 = e0 - E;
        d1 = e1 - E;
    } else {
        d0 = (e0 < E) ? (g_is64 ? e32[2 * E + 2 * e0] : e32[E + e0]) : e0 - E;
        d1 = has1 ? ((e1 < E) ? (g_is64 ? e32[2 * E + 2 * e1] : e32[E + e1]) : e1 - E) : 0;
    }
    int r0 = atomicAdd(&g_deg[d0], 1);
    if (has1) {
        int r1 = atomicAdd(&g_deg[d1], 1);
        *(int2*)&g_rank[e0] = make_int2(r0, r1);
    } else {
        g_rank[e0] = r0;
    }
}

// ---------------- fused + interleaved: degree blocks + HMMA GEMM blocks ----------------
__global__ void __launch_bounds__(512, 2) gemm_degree_kernel(
        const float* __restrict__ X,
        const float* __restrict__ att_src,
        const float* __restrict__ att_dst,
        const int* __restrict__ e32,
        int N, int E, int degBlocks, int gemmBlocks) {
    __shared__ __half sA[64][72];
    __shared__ __half sB[64][264];

    int b = blockIdx.x;
    int mn = degBlocks < gemmBlocks ? degBlocks : gemmBlocks;
    int nI = 2 * mn;
    bool isDeg;
    int idx;
    if (b < nI) { isDeg = (b & 1) == 0; idx = b >> 1; }
    else        { isDeg = degBlocks > gemmBlocks; idx = mn + (b - nI); }

    if (isDeg) {
        degree_role(e32, N, E, idx);
        return;
    }
    int row0 = idx * 64;
    int t = threadIdx.x;

    #pragma unroll
    for (int i = t; i < 2048; i += 512) {
        int idx2 = i * 8;
        int k = idx2 >> 8, n = idx2 & 255;
        *(uint4*)&sB[k][n] = *(const uint4*)&g_wh[idx2];
    }
    #pragma unroll
    for (int i = t; i < 1024; i += 512) {
        int idx2 = i * 4;
        int r = idx2 >> 6, k = idx2 & 63;
        int row = row0 + r;
        float4 v = (row < N) ? *(const float4*)&X[row * 64 + k]
                             : make_float4(0.f, 0.f, 0.f, 0.f);
        *(__half2*)&sA[r][k]     = __floats2half2_rn(v.x, v.y);
        *(__half2*)&sA[r][k + 2] = __floats2half2_rn(v.z, v.w);
    }
    __syncthreads();

    int w = t >> 5, lane = t & 31;
    int wr = (w & 3) * 16;
    int h  = w >> 2;
    int wc = h * 64;
    int m8 = lane >> 3, i8 = lane & 7;
    int rg = (m8 & 1) * 8 + i8;
    int cg = (m8 >> 1) * 8;

    float acc[8][4] = {};

    #pragma unroll
    for (int ki = 0; ki < 4; ki++) {
        uint32_t a0, a1, a2, a3;
        {
            uint32_t addr = (uint32_t)__cvta_generic_to_shared(
                &sA[wr + rg][ki * 16 + cg]);
            asm volatile("ldmatrix.sync.aligned.m8n8.x4.shared.b16 {%0,%1,%2,%3}, [%4];"
                         : "=r"(a0), "=r"(a1), "=r"(a2), "=r"(a3) : "r"(addr));
        }
        #pragma unroll
        for (int nj = 0; nj < 4; nj++) {
            uint32_t b0, b1, b2, b3;
            uint32_t addr = (uint32_t)__cvta_generic_to_shared(
                &sB[ki * 16 + rg][wc + nj * 16 + cg]);
            asm volatile("ldmatrix.sync.aligned.m8n8.x4.trans.shared.b16 {%0,%1,%2,%3}, [%4];"
                         : "=r"(b0), "=r"(b1), "=r"(b2), "=r"(b3) : "r"(addr));
            asm volatile(
                "mma.sync.aligned.m16n8k16.row.col.f32.f16.f16.f32 "
                "{%0,%1,%2,%3}, {%4,%5,%6,%7}, {%8,%9}, {%0,%1,%2,%3};"
                : "+f"(acc[nj * 2][0]), "+f"(acc[nj * 2][1]),
                  "+f"(acc[nj * 2][2]), "+f"(acc[nj * 2][3])
                : "r"(a0), "r"(a1), "r"(a2), "r"(a3), "r"(b0), "r"(b1));
            asm volatile(
                "mma.sync.aligned.m16n8k16.row.col.f32.f16.f16.f32 "
                "{%0,%1,%2,%3}, {%4,%5,%6,%7}, {%8,%9}, {%0,%1,%2,%3};"
                : "+f"(acc[nj * 2 + 1][0]), "+f"(acc[nj * 2 + 1][1]),
                  "+f"(acc[nj * 2 + 1][2]), "+f"(acc[nj * 2 + 1][3])
                : "r"(a0), "r"(a1), "r"(a2), "r"(a3), "r"(b2), "r"(b3));
        }
    }

    // epilogue: fp16 stores in PERMUTED layout + fused attention coefficients.
    // acc[ni] covers head h, cols cc=ni*8+rcol (within head), rows row/row+8.
    // permuted pos (halves) = (cc>>1)*8 + h*2.
    int rrow = lane >> 2, rcol = (lane & 3) * 2;
    int row = row0 + wr + rrow;
    float ps = 0.f, pd = 0.f, ps8 = 0.f, pd8 = 0.f;
    #pragma unroll
    for (int ni = 0; ni < 8; ni++) {
        int cc = ni * 8 + rcol;                 // col within head (even)
        int pos = (cc >> 1) * 8 + h * 2;        // permuted half offset
        if (row < N)
            *(__half2*)&g_xh[row * HC + pos] = __floats2half2_rn(acc[ni][0], acc[ni][1]);
        if (row + 8 < N)
            *(__half2*)&g_xh[(row + 8) * HC + pos] = __floats2half2_rn(acc[ni][2], acc[ni][3]);
        int col = wc + cc;
        float2 as2 = *(const float2*)&att_src[col];
        float2 ad2 = *(const float2*)&att_dst[col];
        ps  += acc[ni][0] * as2.x + acc[ni][1] * as2.y;
        pd  += acc[ni][0] * ad2.x + acc[ni][1] * ad2.y;
        ps8 += acc[ni][2] * as2.x + acc[ni][3] * as2.y;
        pd8 += acc[ni][2] * ad2.x + acc[ni][3] * ad2.y;
    }
    #pragma unroll
    for (int o = 1; o < 4; o <<= 1) {
        ps  += __shfl_xor_sync(0xffffffffu, ps,  o);
        pd  += __shfl_xor_sync(0xffffffffu, pd,  o);
        ps8 += __shfl_xor_sync(0xffffffffu, ps8, o);
        pd8 += __shfl_xor_sync(0xffffffffu, pd8, o);
    }
    if ((lane & 3) == 0) {
        if (row < N) {
            g_asrc[row * 4 + h] = ps;
            g_adst[row * 4 + h] = pd;
        }
        if (row + 8 < N) {
            g_asrc[(row + 8) * 4 + h] = ps8;
            g_adst[(row + 8) * 4 + h] = pd8;
        }
    }
}

// ---------------- single-pass decoupled-lookback scan: deg -> exclusive g_off ----------------
__global__ void scan_lookback(int N, int ET, int nb) {
    __shared__ int wsum[32];
    __shared__ int s_prev;
    int b = blockIdx.x;
    int t = threadIdx.x, lane = t & 31, wid = t >> 5;
    int i = b * 1024 + t;
    int v = (i < N) ? g_deg[i] : 0;
    int x = v;
    #pragma unroll
    for (int o = 1; o < 32; o <<= 1) {
        int y = __shfl_up_sync(0xffffffffu, x, o);
        if (lane >= o) x += y;
    }
    if (lane == 31) wsum[wid] = x;
    if (t == 0) s_prev = 0;
    __syncthreads();
    if (wid == 0) {
        int w = wsum[lane];
        #pragma unroll
        for (int o = 1; o < 32; o <<= 1) {
            int y = __shfl_up_sync(0xffffffffu, w, o);
            if (lane >= o) w += y;
        }
        wsum[lane] = w;
    }
    __syncthreads();
    int agg = wsum[31];
    if (t == 0) atomicExch(&g_flag[b], agg + 1);
    if (t < b) {
        int f;
        do { f = atomicAdd(&g_flag[t], 0); } while (f == 0);
        atomicAdd(&s_prev, f - 1);
    }
    __syncthreads();
    int base = s_prev;
    int ex = (wid ? wsum[wid - 1] : 0) + x - v;
    if (i < N) g_off[i] = base + ex;
    if (b == nb - 1 && t == 0) g_off[N] = ET;
}

// ---------------- edge pass 2: 2 edges per thread; h2exp ----------------
__device__ __forceinline__ float4 make_rec(int s, const float4& as, const float4& ad) {
    float l0 = as.x + ad.x, l1 = as.y + ad.y, l2 = as.z + ad.z, l3 = as.w + ad.w;
    l0 = l0 > 0.f ? l0 : 0.2f * l0;
    l1 = l1 > 0.f ? l1 : 0.2f * l1;
    l2 = l2 > 0.f ? l2 : 0.2f * l2;
    l3 = l3 > 0.f ? l3 : 0.2f * l3;
    __half2 e01 = h2exp(__floats2half2_rn(l0, l1));
    __half2 e23 = h2exp(__floats2half2_rn(l2, l3));
    float4 rec;
    rec.x = __int_as_float(s);
    rec.y = __uint_as_float(*(const unsigned int*)&e01);
    rec.z = __uint_as_float(*(const unsigned int*)&e23);
    rec.w = 0.0f;
    return rec;
}

__global__ void edge_pass2(const int* __restrict__ e32, int N, int E) {
    int p = blockIdx.x * blockDim.x + threadIdx.x;
    int ET = E + N;
    int e0 = 2 * p, e1 = 2 * p + 1;
    if (e0 >= ET) return;
    bool has1 = (e1 < ET);
    int s0, d0, s1 = 0, d1 = 0;
    if (e1 < E) {
        if (g_is64) {
            int4 vs = *(const int4*)&e32[4 * p];
            int4 vd = *(const int4*)&e32[2 * E + 4 * p];
            s0 = vs.x; s1 = vs.z; d0 = vd.x; d1 = vd.z;
        } else {
            int2 vs = *(const int2*)&e32[2 * p];
            int2 vd = *(const int2*)&e32[E + 2 * p];
            s0 = vs.x; s1 = vs.y; d0 = vd.x; d1 = vd.y;
        }
    } else if (e0 >= E) {
        s0 = d0 = e0 - E;
        s1 = d1 = e1 - E;
    } else {
        if (e0 < E) {
            s0 = g_is64 ? e32[2 * e0] : e32[e0];
            d0 = g_is64 ? e32[2 * E + 2 * e0] : e32[E + e0];
        } else { s0 = d0 = e0 - E; }
        if (has1) {
            if (e1 < E) {
                s1 = g_is64 ? e32[2 * e1] : e32[e1];
                d1 = g_is64 ? e32[2 * E + 2 * e1] : e32[E + e1];
            } else { s1 = d1 = e1 - E; }
        }
    }
    float4 as0 = *(const float4*)&g_asrc[s0 * 4];
    float4 ad0 = *(const float4*)&g_adst[d0 * 4];
    float4 as1, ad1;
    if (has1) {
        as1 = *(const float4*)&g_asrc[s1 * 4];
        ad1 = *(const float4*)&g_adst[d1 * 4];
    }
    int2 rk = has1 ? *(const int2*)&g_rank[e0] : make_int2(g_rank[e0], 0);
    float4 rec0 = make_rec(s0, as0, ad0);
    g_pack[g_off[d0] + rk.x] = rec0;
    if (has1) {
        float4 rec1 = make_rec(s1, as1, ad1);
        g_pack[g_off[d1] + rk.y] = rec1;
    }
}

// ---------------- warp-per-dst-node aggregation; permuted layout: 1 LDG.128 gather/edge ----------------
__global__ void aggregate_kernel(const float* __restrict__ bias,
                                 float* __restrict__ out, int N) {
    int gw = (blockIdx.x * blockDim.x + threadIdx.x) >> 5;
    int lane = threadIdx.x & 31;
    if (gw >= N) return;
    int beg = g_off[gw], end = g_off[gw + 1];
    float a00 = 0.f, a01 = 0.f, a10 = 0.f, a11 = 0.f;
    float a20 = 0.f, a21 = 0.f, a30 = 0.f, a31 = 0.f;
    float s0 = 0.f, s1 = 0.f, s2 = 0.f, s3 = 0.f;
    for (int j = beg; j < end; j++) {
        float4 rec = g_pack[j];
        int s = __float_as_int(rec.x);
        unsigned int u01 = __float_as_uint(rec.y);
        unsigned int u23 = __float_as_uint(rec.z);
        float2 w01 = __half22float2(*(const __half2*)&u01);
        float2 w23 = __half22float2(*(const __half2*)&u23);
        // permuted row: lane = col pair; uint4 = heads 0..3 half2s
        uint4 xv = *(const uint4*)&g_xh[s * HC + lane * 8];
        float2 v0 = __half22float2(*(const __half2*)&xv.x);
        float2 v1 = __half22float2(*(const __half2*)&xv.y);
        float2 v2 = __half22float2(*(const __half2*)&xv.z);
        float2 v3 = __half22float2(*(const __half2*)&xv.w);
        a00 += w01.x * v0.x; a01 += w01.x * v0.y;
        a10 += w01.y * v1.x; a11 += w01.y * v1.y;
        a20 += w23.x * v2.x; a21 += w23.x * v2.y;
        a30 += w23.y * v3.x; a31 += w23.y * v3.y;
        s0 += w01.x; s1 += w01.y; s2 += w23.x; s3 += w23.y;
    }
    float n0 = 0.25f / (s0 + 1e-16f);
    float n1 = 0.25f / (s1 + 1e-16f);
    float n2 = 0.25f / (s2 + 1e-16f);
    float n3 = 0.25f / (s3 + 1e-16f);
    int c = 2 * lane;
    float o0 = a00 * n0 + a10 * n1 + a20 * n2 + a30 * n3 + bias[c];
    float o1 = a01 * n0 + a11 * n1 + a21 * n2 + a31 * n3 + bias[c + 1];
    *(float2*)&out[gw * 64 + c] = make_float2(o0, o1);
}

// ---------------- launch ----------------
extern "C" void kernel_launch(void* const* d_in, const int* in_sizes, int n_in,
                              void* d_out, int out_size) {
    const float* meta_x  = (const float*)d_in[0];
    const int*   edge32  = (const int*)d_in[1];
    const float* W       = (const float*)d_in[2];
    const float* att_src = (const float*)d_in[3];
    const float* att_dst = (const float*)d_in[4];
    const float* bias    = (const float*)d_in[5];
    float*       out     = (float*)d_out;

    int N  = in_sizes[0] / 64;
    int E  = in_sizes[1] / 2;
    int ET = E + N;
    int nb = (N + 1023) / 1024;
    int np = (ET + 1) / 2;
    int degBlocks  = (np + 511) / 512;
    int gemmBlocks = (N + 63) / 64;

    detect_init_wh_kernel<<<(N + 255) / 256, 256>>>(edge32, W, N);
    gemm_degree_kernel<<<degBlocks + gemmBlocks, 512>>>(meta_x, att_src, att_dst,
                                                        edge32, N, E, degBlocks, gemmBlocks);
    scan_lookback<<<nb, 1024>>>(N, ET, nb);
    edge_pass2<<<(np + 255) / 256, 256>>>(edge32, N, E);
    aggregate_kernel<<<(N * 32 + 255) / 256, 256>>>(bias, out, N);
}

// round 16
// speedup vs baseline: 1.0631x; 1.0208x over previous
#include <cuda_runtime.h>
#include <cuda_fp16.h>
#include <cstdint>

// Problem constants (from reference): N=50000, DIM=64, HEADS=4, E=800000.
#define MAXN 50000
#define MAXE 800000
#define MAXET (MAXE + MAXN)
#define HC 256   // HEADS * DIM

// ---------------- scratch (static device globals; no allocation) ----------------
__device__ __align__(16) __half g_xh[MAXN * HC];      // [N, H, C] = x @ W  (fp16, head-major)
__device__ __align__(16) __half g_wh[64 * 256];       // fp16 copy of W
__device__ __align__(16) float g_asrc[MAXN * 4];      // [N, H]
__device__ __align__(16) float g_adst[MAXN * 4];      // [N, H]
__device__ int    g_deg[MAXN];
__device__ int    g_off[MAXN + 1];
__device__ int    g_flag[64];                         // lookback: 0=unready else agg+1
__device__ __align__(16) int g_rank[MAXET];           // within-dst rank of each edge
__device__ float4 g_pack[MAXET];                      // CSR rec: {src:int, exp01:h2, exp23:h2, pad}
__device__ int    g_is64;                             // 1 if edge buffer is int64

// ---------------- f32x2 packed math helpers (Blackwell) ----------------
__device__ __forceinline__ unsigned long long pk2(float x, float y) {
    unsigned long long r;
    asm("mov.b64 %0, {%1, %2};" : "=l"(r)
        : "r"(__float_as_uint(x)), "r"(__float_as_uint(y)));
    return r;
}
__device__ __forceinline__ void upk2(unsigned long long v, float& x, float& y) {
    unsigned int lo, hi;
    asm("mov.b64 {%0, %1}, %2;" : "=r"(lo), "=r"(hi) : "l"(v));
    x = __uint_as_float(lo); y = __uint_as_float(hi);
}
#define FMA2(acc, a, b) asm("fma.rn.f32x2 %0, %1, %2, %0;" : "+l"(acc) : "l"(a), "l"(b))
#define ADD2(acc, a)    asm("add.rn.f32x2 %0, %1, %0;"     : "+l"(acc) : "l"(a))

// ---------------- detect int64/int32 + init counters/flags + W->fp16 (merged) ----------------
__global__ void detect_init_wh_kernel(const int* __restrict__ e32,
                                      const float* __restrict__ W, int N) {
    int i = blockIdx.x * blockDim.x + threadIdx.x;
    if (i < N) g_deg[i] = 0;
    if (i < 64) g_flag[i] = 0;
    if (blockIdx.x == 0) {
        __shared__ int s_any;
        if (threadIdx.x == 0) s_any = 0;
        __syncthreads();
        int any = 0;
        for (int k = threadIdx.x; k < 2048; k += blockDim.x)
            any |= e32[2 * k + 1];
        if (any) atomicOr(&s_any, 1);
        __syncthreads();
        if (threadIdx.x == 0) g_is64 = s_any ? 0 : 1;
    } else if (blockIdx.x <= 16) {
        int j = (blockIdx.x - 1) * 256 + threadIdx.x;   // 0..4095, 4 floats each
        float4 v = *(const float4*)&W[j * 4];
        *(__half2*)&g_wh[j * 4]     = __floats2half2_rn(v.x, v.y);
        *(__half2*)&g_wh[j * 4 + 2] = __floats2half2_rn(v.z, v.w);
    }
}

// ---------------- degree role: 512 threads, 2 edges per thread ----------------
__device__ __forceinline__ void degree_role(const int* __restrict__ e32,
                                            int N, int E, int blk) {
    int p = blk * 512 + threadIdx.x;
    int ET = E + N;
    int e0 = 2 * p, e1 = 2 * p + 1;
    if (e0 >= ET) return;
    bool has1 = (e1 < ET);
    int d0, d1 = 0;
    if (e1 < E) {
        if (g_is64) {
            int4 v = *(const int4*)&e32[2 * E + 4 * p];
            d0 = v.x; d1 = v.z;
        } else {
            int2 v = *(const int2*)&e32[E + 2 * p];
            d0 = v.x; d1 = v.y;
        }
    } else if (e0 >= E) {
        d0 = e0 - E;
        d1 = e1 - E;
    } else {
        d0 = (e0 < E) ? (g_is64 ? e32[2 * E + 2 * e0] : e32[E + e0]) : e0 - E;
        d1 = has1 ? ((e1 < E) ? (g_is64 ? e32[2 * E + 2 * e1] : e32[E + e1]) : e1 - E) : 0;
    }
    int r0 = atomicAdd(&g_deg[d0], 1);
    if (has1) {
        int r1 = atomicAdd(&g_deg[d1], 1);
        *(int2*)&g_rank[e0] = make_int2(r0, r1);
    } else {
        g_rank[e0] = r0;
    }
}

// ---------------- fused + interleaved: degree blocks + HMMA GEMM blocks ----------------
__global__ void __launch_bounds__(512, 2) gemm_degree_kernel(
        const float* __restrict__ X,
        const float* __restrict__ att_src,
        const float* __restrict__ att_dst,
        const int* __restrict__ e32,
        int N, int E, int degBlocks, int gemmBlocks) {
    __shared__ __half sA[64][72];
    __shared__ __half sB[64][264];

    int b = blockIdx.x;
    int mn = degBlocks < gemmBlocks ? degBlocks : gemmBlocks;
    int nI = 2 * mn;
    bool isDeg;
    int idx;
    if (b < nI) { isDeg = (b & 1) == 0; idx = b >> 1; }
    else        { isDeg = degBlocks > gemmBlocks; idx = mn + (b - nI); }

    if (isDeg) {
        degree_role(e32, N, E, idx);
        return;
    }
    int row0 = idx * 64;
    int t = threadIdx.x;

    #pragma unroll
    for (int i = t; i < 2048; i += 512) {
        int idx2 = i * 8;
        int k = idx2 >> 8, n = idx2 & 255;
        *(uint4*)&sB[k][n] = *(const uint4*)&g_wh[idx2];
    }
    #pragma unroll
    for (int i = t; i < 1024; i += 512) {
        int idx2 = i * 4;
        int r = idx2 >> 6, k = idx2 & 63;
        int row = row0 + r;
        float4 v = (row < N) ? *(const float4*)&X[row * 64 + k]
                             : make_float4(0.f, 0.f, 0.f, 0.f);
        *(__half2*)&sA[r][k]     = __floats2half2_rn(v.x, v.y);
        *(__half2*)&sA[r][k + 2] = __floats2half2_rn(v.z, v.w);
    }
    __syncthreads();

    int w = t >> 5, lane = t & 31;
    int wr = (w & 3) * 16;
    int h  = w >> 2;
    int wc = h * 64;
    int m8 = lane >> 3, i8 = lane & 7;
    int rg = (m8 & 1) * 8 + i8;
    int cg = (m8 >> 1) * 8;

    float acc[8][4] = {};

    #pragma unroll
    for (int ki = 0; ki < 4; ki++) {
        uint32_t a0, a1, a2, a3;
        {
            uint32_t addr = (uint32_t)__cvta_generic_to_shared(
                &sA[wr + rg][ki * 16 + cg]);
            asm volatile("ldmatrix.sync.aligned.m8n8.x4.shared.b16 {%0,%1,%2,%3}, [%4];"
                         : "=r"(a0), "=r"(a1), "=r"(a2), "=r"(a3) : "r"(addr));
        }
        #pragma unroll
        for (int nj = 0; nj < 4; nj++) {
            uint32_t b0, b1, b2, b3;
            uint32_t addr = (uint32_t)__cvta_generic_to_shared(
                &sB[ki * 16 + rg][wc + nj * 16 + cg]);
            asm volatile("ldmatrix.sync.aligned.m8n8.x4.trans.shared.b16 {%0,%1,%2,%3}, [%4];"
                         : "=r"(b0), "=r"(b1), "=r"(b2), "=r"(b3) : "r"(addr));
            asm volatile(
                "mma.sync.aligned.m16n8k16.row.col.f32.f16.f16.f32 "
                "{%0,%1,%2,%3}, {%4,%5,%6,%7}, {%8,%9}, {%0,%1,%2,%3};"
                : "+f"(acc[nj * 2][0]), "+f"(acc[nj * 2][1]),
                  "+f"(acc[nj * 2][2]), "+f"(acc[nj * 2][3])
                : "r"(a0), "r"(a1), "r"(a2), "r"(a3), "r"(b0), "r"(b1));
            asm volatile(
                "mma.sync.aligned.m16n8k16.row.col.f32.f16.f16.f32 "
                "{%0,%1,%2,%3}, {%4,%5,%6,%7}, {%8,%9}, {%0,%1,%2,%3};"
                : "+f"(acc[nj * 2 + 1][0]), "+f"(acc[nj * 2 + 1][1]),
                  "+f"(acc[nj * 2 + 1][2]), "+f"(acc[nj * 2 + 1][3])
                : "r"(a0), "r"(a1), "r"(a2), "r"(a3), "r"(b2), "r"(b3));
        }
    }

    int rrow = lane >> 2, rcol = (lane & 3) * 2;
    int row = row0 + wr + rrow;
    float ps = 0.f, pd = 0.f, ps8 = 0.f, pd8 = 0.f;
    #pragma unroll
    for (int ni = 0; ni < 8; ni++) {
        int col = wc + ni * 8 + rcol;
        if (row < N)
            *(__half2*)&g_xh[row * HC + col] = __floats2half2_rn(acc[ni][0], acc[ni][1]);
        if (row + 8 < N)
            *(__half2*)&g_xh[(row + 8) * HC + col] = __floats2half2_rn(acc[ni][2], acc[ni][3]);
        float2 as2 = *(const float2*)&att_src[col];
        float2 ad2 = *(const float2*)&att_dst[col];
        ps  += acc[ni][0] * as2.x + acc[ni][1] * as2.y;
        pd  += acc[ni][0] * ad2.x + acc[ni][1] * ad2.y;
        ps8 += acc[ni][2] * as2.x + acc[ni][3] * as2.y;
        pd8 += acc[ni][2] * ad2.x + acc[ni][3] * ad2.y;
    }
    #pragma unroll
    for (int o = 1; o < 4; o <<= 1) {
        ps  += __shfl_xor_sync(0xffffffffu, ps,  o);
        pd  += __shfl_xor_sync(0xffffffffu, pd,  o);
        ps8 += __shfl_xor_sync(0xffffffffu, ps8, o);
        pd8 += __shfl_xor_sync(0xffffffffu, pd8, o);
    }
    if ((lane & 3) == 0) {
        if (row < N) {
            g_asrc[row * 4 + h] = ps;
            g_adst[row * 4 + h] = pd;
        }
        if (row + 8 < N) {
            g_asrc[(row + 8) * 4 + h] = ps8;
            g_adst[(row + 8) * 4 + h] = pd8;
        }
    }
}

// ---------------- single-pass decoupled-lookback scan: deg -> exclusive g_off ----------------
__global__ void scan_lookback(int N, int ET, int nb) {
    __shared__ int wsum[32];
    __shared__ int s_prev;
    int b = blockIdx.x;
    int t = threadIdx.x, lane = t & 31, wid = t >> 5;
    int i = b * 1024 + t;
    int v = (i < N) ? g_deg[i] : 0;
    int x = v;
    #pragma unroll
    for (int o = 1; o < 32; o <<= 1) {
        int y = __shfl_up_sync(0xffffffffu, x, o);
        if (lane >= o) x += y;
    }
    if (lane == 31) wsum[wid] = x;
    if (t == 0) s_prev = 0;
    __syncthreads();
    if (wid == 0) {
        int w = wsum[lane];
        #pragma unroll
        for (int o = 1; o < 32; o <<= 1) {
            int y = __shfl_up_sync(0xffffffffu, w, o);
            if (lane >= o) w += y;
        }
        wsum[lane] = w;
    }
    __syncthreads();
    int agg = wsum[31];
    if (t == 0) atomicExch(&g_flag[b], agg + 1);
    if (t < b) {
        int f;
        do { f = atomicAdd(&g_flag[t], 0); } while (f == 0);
        atomicAdd(&s_prev, f - 1);
    }
    __syncthreads();
    int base = s_prev;
    int ex = (wid ? wsum[wid - 1] : 0) + x - v;
    if (i < N) g_off[i] = base + ex;
    if (b == nb - 1 && t == 0) g_off[N] = ET;
}

// ---------------- edge pass 2: 4 edges per thread (MLP=8 on a-coef gathers) ----------------
__device__ __forceinline__ float4 make_rec(int s, const float4& as, const float4& ad) {
    float l0 = as.x + ad.x, l1 = as.y + ad.y, l2 = as.z + ad.z, l3 = as.w + ad.w;
    l0 = l0 > 0.f ? l0 : 0.2f * l0;
    l1 = l1 > 0.f ? l1 : 0.2f * l1;
    l2 = l2 > 0.f ? l2 : 0.2f * l2;
    l3 = l3 > 0.f ? l3 : 0.2f * l3;
    __half2 e01 = h2exp(__floats2half2_rn(l0, l1));
    __half2 e23 = h2exp(__floats2half2_rn(l2, l3));
    float4 rec;
    rec.x = __int_as_float(s);
    rec.y = __uint_as_float(*(const unsigned int*)&e01);
    rec.z = __uint_as_float(*(const unsigned int*)&e23);
    rec.w = 0.0f;
    return rec;
}

__global__ void edge_pass2(const int* __restrict__ e32, int N, int E) {
    int q = blockIdx.x * blockDim.x + threadIdx.x;   // quad index
    int ET = E + N;
    int e0 = 4 * q;
    if (e0 >= ET) return;
    int cnt = (ET - e0 < 4) ? (ET - e0) : 4;
    int s[4], d[4];
    if (e0 + 3 < E) {                       // all real edges (fast path)
        if (g_is64) {
            int4 va = *(const int4*)&e32[8 * q];
            int4 vb = *(const int4*)&e32[8 * q + 4];
            int4 vc = *(const int4*)&e32[2 * E + 8 * q];
            int4 vd4 = *(const int4*)&e32[2 * E + 8 * q + 4];
            s[0] = va.x; s[1] = va.z; s[2] = vb.x; s[3] = vb.z;
            d[0] = vc.x; d[1] = vc.z; d[2] = vd4.x; d[3] = vd4.z;
        } else {
            int4 vs = *(const int4*)&e32[4 * q];
            int4 vd4 = *(const int4*)&e32[E + 4 * q];
            s[0] = vs.x; s[1] = vs.y; s[2] = vs.z; s[3] = vs.w;
            d[0] = vd4.x; d[1] = vd4.y; d[2] = vd4.z; d[3] = vd4.w;
        }
    } else if (e0 >= E) {                   // all self loops
        #pragma unroll
        for (int k = 0; k < 4; k++) { s[k] = d[k] = e0 + k - E; }
    } else {                                // mixed (scalar)
        #pragma unroll
        for (int k = 0; k < 4; k++) {
            int e = e0 + k;
            if (e < E) {
                s[k] = g_is64 ? e32[2 * e] : e32[e];
                d[k] = g_is64 ? e32[2 * E + 2 * e] : e32[E + e];
            } else {
                s[k] = d[k] = (e - E < N) ? (e - E) : 0;   // safe for k >= cnt
            }
        }
    }
    // independent gathers (MLP up to 8)
    float4 as[4], ad[4];
    #pragma unroll
    for (int k = 0; k < 4; k++) {
        if (k < cnt) {
            as[k] = *(const float4*)&g_asrc[s[k] * 4];
            ad[k] = *(const float4*)&g_adst[d[k] * 4];
        }
    }
    int4 rk;
    if (cnt == 4) rk = *(const int4*)&g_rank[e0];
    else {
        int* rp = (int*)&rk;
        for (int k = 0; k < cnt; k++) rp[k] = g_rank[e0 + k];
    }
    const int* rkp = (const int*)&rk;
    #pragma unroll
    for (int k = 0; k < 4; k++) {
        if (k < cnt) {
            float4 rec = make_rec(s[k], as[k], ad[k]);
            g_pack[g_off[d[k]] + rkp[k]] = rec;
        }
    }
}

// ---------------- warp-per-dst-node aggregation; f32x2 packed FMA ----------------
__global__ void aggregate_kernel(const float* __restrict__ bias,
                                 float* __restrict__ out, int N) {
    int gw = (blockIdx.x * blockDim.x + threadIdx.x) >> 5;
    int lane = threadIdx.x & 31;
    if (gw >= N) return;
    int beg = g_off[gw], end = g_off[gw + 1];

    unsigned long long A0 = 0ull, A1 = 0ull, A2 = 0ull, A3 = 0ull;  // (a_h0, a_h0'), ...
    unsigned long long S01 = 0ull, S23 = 0ull;                      // (s0,s1), (s2,s3)

    for (int j = beg; j < end; j++) {
        float4 rec = g_pack[j];
        int s = __float_as_int(rec.x);
        unsigned int u01 = __float_as_uint(rec.y);
        unsigned int u23 = __float_as_uint(rec.z);
        float2 w01 = __half22float2(*(const __half2*)&u01);
        float2 w23 = __half22float2(*(const __half2*)&u23);
        // segsum (packed)
        ADD2(S01, pk2(w01.x, w01.y));
        ADD2(S23, pk2(w23.x, w23.y));
        // broadcast weights
        unsigned long long wA = pk2(w01.x, w01.x);
        unsigned long long wB = pk2(w01.y, w01.y);
        unsigned long long wC = pk2(w23.x, w23.x);
        unsigned long long wD = pk2(w23.y, w23.y);
        const __half2* xr = (const __half2*)(g_xh + s * HC);
        float2 v0 = __half22float2(xr[lane]);
        float2 v1 = __half22float2(xr[32 + lane]);
        float2 v2 = __half22float2(xr[64 + lane]);
        float2 v3 = __half22float2(xr[96 + lane]);
        FMA2(A0, wA, pk2(v0.x, v0.y));
        FMA2(A1, wB, pk2(v1.x, v1.y));
        FMA2(A2, wC, pk2(v2.x, v2.y));
        FMA2(A3, wD, pk2(v3.x, v3.y));
    }
    float a00, a01, a10, a11, a20, a21, a30, a31, s0, s1, s2, s3;
    upk2(A0, a00, a01); upk2(A1, a10, a11);
    upk2(A2, a20, a21); upk2(A3, a30, a31);
    upk2(S01, s0, s1);  upk2(S23, s2, s3);

    float n0 = 0.25f / (s0 + 1e-16f);
    float n1 = 0.25f / (s1 + 1e-16f);
    float n2 = 0.25f / (s2 + 1e-16f);
    float n3 = 0.25f / (s3 + 1e-16f);
    int c = 2 * lane;
    float o0 = a00 * n0 + a10 * n1 + a20 * n2 + a30 * n3 + bias[c];
    float o1 = a01 * n0 + a11 * n1 + a21 * n2 + a31 * n3 + bias[c + 1];
    *(float2*)&out[gw * 64 + c] = make_float2(o0, o1);
}

// ---------------- launch ----------------
extern "C" void kernel_launch(void* const* d_in, const int* in_sizes, int n_in,
                              void* d_out, int out_size) {
    const float* meta_x  = (const float*)d_in[0];
    const int*   edge32  = (const int*)d_in[1];
    const float* W       = (const float*)d_in[2];
    const float* att_src = (const float*)d_in[3];
    const float* att_dst = (const float*)d_in[4];
    const float* bias    = (const float*)d_in[5];
    float*       out     = (float*)d_out;

    int N  = in_sizes[0] / 64;
    int E  = in_sizes[1] / 2;
    int ET = E + N;
    int nb = (N + 1023) / 1024;
    int np = (ET + 1) / 2;
    int nq = (ET + 3) / 4;
    int degBlocks  = (np + 511) / 512;
    int gemmBlocks = (N + 63) / 64;

    detect_init_wh_kernel<<<(N + 255) / 256, 256>>>(edge32, W, N);
    gemm_degree_kernel<<<degBlocks + gemmBlocks, 512>>>(meta_x, att_src, att_dst,
                                                        edge32, N, E, degBlocks, gemmBlocks);
    scan_lookback<<<nb, 1024>>>(N, ET, nb);
    edge_pass2<<<(nq + 255) / 256, 256>>>(edge32, N, E);
    aggregate_kernel<<<(N * 32 + 255) / 256, 256>>>(bias, out, N);
}

// round 17
// speedup vs baseline: 1.0900x; 1.0253x over previous
#include <cuda_runtime.h>
#include <cuda_fp16.h>
#include <cstdint>

// Problem constants (from reference): N=50000, DIM=64, HEADS=4, E=800000.
#define MAXN 50000
#define MAXE 800000
#define MAXET (MAXE + MAXN)
#define HC 256   // HEADS * DIM

// ---------------- scratch (static device globals; no allocation) ----------------
__device__ __align__(16) __half g_xh[MAXN * HC];      // [N, H, C] = x @ W  (fp16, head-major)
__device__ __align__(16) __half g_wh[64 * 256];       // fp16 copy of W
__device__ __align__(16) float g_asrc[MAXN * 4];      // [N, H]
__device__ __align__(16) float g_adst[MAXN * 4];      // [N, H]
__device__ int    g_deg[MAXN];
__device__ int    g_off[MAXN + 1];
__device__ int    g_flag[64];                         // lookback: 0=unready else agg+1
__device__ __align__(8) int g_rank[MAXET];            // within-dst rank of each edge
__device__ float4 g_pack[MAXET];                      // CSR rec: {src:int, exp01:h2, exp23:h2, pad}
__device__ int    g_is64;                             // 1 if edge buffer is int64

// ---------------- f32x2 packed math helpers (Blackwell) ----------------
__device__ __forceinline__ unsigned long long pk2(float x, float y) {
    unsigned long long r;
    asm("mov.b64 %0, {%1, %2};" : "=l"(r)
        : "r"(__float_as_uint(x)), "r"(__float_as_uint(y)));
    return r;
}
__device__ __forceinline__ void upk2(unsigned long long v, float& x, float& y) {
    unsigned int lo, hi;
    asm("mov.b64 {%0, %1}, %2;" : "=r"(lo), "=r"(hi) : "l"(v));
    x = __uint_as_float(lo); y = __uint_as_float(hi);
}
#define FMA2(acc, a, b) asm("fma.rn.f32x2 %0, %1, %2, %0;" : "+l"(acc) : "l"(a), "l"(b))
#define ADD2(acc, a)    asm("add.rn.f32x2 %0, %1, %0;"     : "+l"(acc) : "l"(a))

// ---------------- detect int64/int32 + init counters/flags + W->fp16 (merged) ----------------
__global__ void detect_init_wh_kernel(const int* __restrict__ e32,
                                      const float* __restrict__ W, int N) {
    int i = blockIdx.x * blockDim.x + threadIdx.x;
    if (i < N) g_deg[i] = 0;
    if (i < 64) g_flag[i] = 0;
    if (blockIdx.x == 0) {
        __shared__ int s_any;
        if (threadIdx.x == 0) s_any = 0;
        __syncthreads();
        int any = 0;
        for (int k = threadIdx.x; k < 2048; k += blockDim.x)
            any |= e32[2 * k + 1];
        if (any) atomicOr(&s_any, 1);
        __syncthreads();
        if (threadIdx.x == 0) g_is64 = s_any ? 0 : 1;
    } else if (blockIdx.x <= 16) {
        int j = (blockIdx.x - 1) * 256 + threadIdx.x;   // 0..4095, 4 floats each
        float4 v = *(const float4*)&W[j * 4];
        *(__half2*)&g_wh[j * 4]     = __floats2half2_rn(v.x, v.y);
        *(__half2*)&g_wh[j * 4 + 2] = __floats2half2_rn(v.z, v.w);
    }
}

// ---------------- degree role: 512 threads, 2 edges per thread ----------------
__device__ __forceinline__ void degree_role(const int* __restrict__ e32,
                                            int N, int E, int blk) {
    int p = blk * 512 + threadIdx.x;
    int ET = E + N;
    int e0 = 2 * p, e1 = 2 * p + 1;
    if (e0 >= ET) return;
    bool has1 = (e1 < ET);
    int d0, d1 = 0;
    if (e1 < E) {
        if (g_is64) {
            int4 v = *(const int4*)&e32[2 * E + 4 * p];
            d0 = v.x; d1 = v.z;
        } else {
            int2 v = *(const int2*)&e32[E + 2 * p];
            d0 = v.x; d1 = v.y;
        }
    } else if (e0 >= E) {
        d0 = e0 - E;
        d1 = e1 - E;
    } else {
        d0 = (e0 < E) ? (g_is64 ? e32[2 * E + 2 * e0] : e32[E + e0]) : e0 - E;
        d1 = has1 ? ((e1 < E) ? (g_is64 ? e32[2 * E + 2 * e1] : e32[E + e1]) : e1 - E) : 0;
    }
    int r0 = atomicAdd(&g_deg[d0], 1);
    if (has1) {
        int r1 = atomicAdd(&g_deg[d1], 1);
        *(int2*)&g_rank[e0] = make_int2(r0, r1);
    } else {
        g_rank[e0] = r0;
    }
}

// ---------------- fused + interleaved: degree blocks + HMMA GEMM blocks ----------------
__global__ void __launch_bounds__(512, 2) gemm_degree_kernel(
        const float* __restrict__ X,
        const float* __restrict__ att_src,
        const float* __restrict__ att_dst,
        const int* __restrict__ e32,
        int N, int E, int degBlocks, int gemmBlocks) {
    __shared__ __half sA[64][72];
    __shared__ __half sB[64][264];

    int b = blockIdx.x;
    int mn = degBlocks < gemmBlocks ? degBlocks : gemmBlocks;
    int nI = 2 * mn;
    bool isDeg;
    int idx;
    if (b < nI) { isDeg = (b & 1) == 0; idx = b >> 1; }
    else        { isDeg = degBlocks > gemmBlocks; idx = mn + (b - nI); }

    if (isDeg) {
        degree_role(e32, N, E, idx);
        return;
    }
    int row0 = idx * 64;
    int t = threadIdx.x;

    #pragma unroll
    for (int i = t; i < 2048; i += 512) {
        int idx2 = i * 8;
        int k = idx2 >> 8, n = idx2 & 255;
        *(uint4*)&sB[k][n] = *(const uint4*)&g_wh[idx2];
    }
    #pragma unroll
    for (int i = t; i < 1024; i += 512) {
        int idx2 = i * 4;
        int r = idx2 >> 6, k = idx2 & 63;
        int row = row0 + r;
        float4 v = (row < N) ? *(const float4*)&X[row * 64 + k]
                             : make_float4(0.f, 0.f, 0.f, 0.f);
        *(__half2*)&sA[r][k]     = __floats2half2_rn(v.x, v.y);
        *(__half2*)&sA[r][k + 2] = __floats2half2_rn(v.z, v.w);
    }
    __syncthreads();

    int w = t >> 5, lane = t & 31;
    int wr = (w & 3) * 16;
    int h  = w >> 2;
    int wc = h * 64;
    int m8 = lane >> 3, i8 = lane & 7;
    int rg = (m8 & 1) * 8 + i8;
    int cg = (m8 >> 1) * 8;

    float acc[8][4] = {};

    #pragma unroll
    for (int ki = 0; ki < 4; ki++) {
        uint32_t a0, a1, a2, a3;
        {
            uint32_t addr = (uint32_t)__cvta_generic_to_shared(
                &sA[wr + rg][ki * 16 + cg]);
            asm volatile("ldmatrix.sync.aligned.m8n8.x4.shared.b16 {%0,%1,%2,%3}, [%4];"
                         : "=r"(a0), "=r"(a1), "=r"(a2), "=r"(a3) : "r"(addr));
        }
        #pragma unroll
        for (int nj = 0; nj < 4; nj++) {
            uint32_t b0, b1, b2, b3;
            uint32_t addr = (uint32_t)__cvta_generic_to_shared(
                &sB[ki * 16 + rg][wc + nj * 16 + cg]);
            asm volatile("ldmatrix.sync.aligned.m8n8.x4.trans.shared.b16 {%0,%1,%2,%3}, [%4];"
                         : "=r"(b0), "=r"(b1), "=r"(b2), "=r"(b3) : "r"(addr));
            asm volatile(
                "mma.sync.aligned.m16n8k16.row.col.f32.f16.f16.f32 "
                "{%0,%1,%2,%3}, {%4,%5,%6,%7}, {%8,%9}, {%0,%1,%2,%3};"
                : "+f"(acc[nj * 2][0]), "+f"(acc[nj * 2][1]),
                  "+f"(acc[nj * 2][2]), "+f"(acc[nj * 2][3])
                : "r"(a0), "r"(a1), "r"(a2), "r"(a3), "r"(b0), "r"(b1));
            asm volatile(
                "mma.sync.aligned.m16n8k16.row.col.f32.f16.f16.f32 "
                "{%0,%1,%2,%3}, {%4,%5,%6,%7}, {%8,%9}, {%0,%1,%2,%3};"
                : "+f"(acc[nj * 2 + 1][0]), "+f"(acc[nj * 2 + 1][1]),
                  "+f"(acc[nj * 2 + 1][2]), "+f"(acc[nj * 2 + 1][3])
                : "r"(a0), "r"(a1), "r"(a2), "r"(a3), "r"(b2), "r"(b3));
        }
    }

    int rrow = lane >> 2, rcol = (lane & 3) * 2;
    int row = row0 + wr + rrow;
    float ps = 0.f, pd = 0.f, ps8 = 0.f, pd8 = 0.f;
    #pragma unroll
    for (int ni = 0; ni < 8; ni++) {
        int col = wc + ni * 8 + rcol;
        if (row < N)
            *(__half2*)&g_xh[row * HC + col] = __floats2half2_rn(acc[ni][0], acc[ni][1]);
        if (row + 8 < N)
            *(__half2*)&g_xh[(row + 8) * HC + col] = __floats2half2_rn(acc[ni][2], acc[ni][3]);
        float2 as2 = *(const float2*)&att_src[col];
        float2 ad2 = *(const float2*)&att_dst[col];
        ps  += acc[ni][0] * as2.x + acc[ni][1] * as2.y;
        pd  += acc[ni][0] * ad2.x + acc[ni][1] * ad2.y;
        ps8 += acc[ni][2] * as2.x + acc[ni][3] * as2.y;
        pd8 += acc[ni][2] * ad2.x + acc[ni][3] * ad2.y;
    }
    #pragma unroll
    for (int o = 1; o < 4; o <<= 1) {
        ps  += __shfl_xor_sync(0xffffffffu, ps,  o);
        pd  += __shfl_xor_sync(0xffffffffu, pd,  o);
        ps8 += __shfl_xor_sync(0xffffffffu, ps8, o);
        pd8 += __shfl_xor_sync(0xffffffffu, pd8, o);
    }
    if ((lane & 3) == 0) {
        if (row < N) {
            g_asrc[row * 4 + h] = ps;
            g_adst[row * 4 + h] = pd;
        }
        if (row + 8 < N) {
            g_asrc[(row + 8) * 4 + h] = ps8;
            g_adst[(row + 8) * 4 + h] = pd8;
        }
    }
}

// ---------------- single-pass decoupled-lookback scan: deg -> exclusive g_off ----------------
__global__ void scan_lookback(int N, int ET, int nb) {
    __shared__ int wsum[32];
    __shared__ int s_prev;
    int b = blockIdx.x;
    int t = threadIdx.x, lane = t & 31, wid = t >> 5;
    int i = b * 1024 + t;
    int v = (i < N) ? g_deg[i] : 0;
    int x = v;
    #pragma unroll
    for (int o = 1; o < 32; o <<= 1) {
        int y = __shfl_up_sync(0xffffffffu, x, o);
        if (lane >= o) x += y;
    }
    if (lane == 31) wsum[wid] = x;
    if (t == 0) s_prev = 0;
    __syncthreads();
    if (wid == 0) {
        int w = wsum[lane];
        #pragma unroll
        for (int o = 1; o < 32; o <<= 1) {
            int y = __shfl_up_sync(0xffffffffu, w, o);
            if (lane >= o) w += y;
        }
        wsum[lane] = w;
    }
    __syncthreads();
    int agg = wsum[31];
    if (t == 0) atomicExch(&g_flag[b], agg + 1);
    if (t < b) {
        int f;
        do { f = atomicAdd(&g_flag[t], 0); } while (f == 0);
        atomicAdd(&s_prev, f - 1);
    }
    __syncthreads();
    int base = s_prev;
    int ex = (wid ? wsum[wid - 1] : 0) + x - v;
    if (i < N) g_off[i] = base + ex;
    if (b == nb - 1 && t == 0) g_off[N] = ET;
}

// ---------------- edge pass 2: 2 edges per thread (R12 form: regs 32, occ ~80%) ----------------
__device__ __forceinline__ float4 make_rec(int s, const float4& as, const float4& ad) {
    float l0 = as.x + ad.x, l1 = as.y + ad.y, l2 = as.z + ad.z, l3 = as.w + ad.w;
    l0 = l0 > 0.f ? l0 : 0.2f * l0;
    l1 = l1 > 0.f ? l1 : 0.2f * l1;
    l2 = l2 > 0.f ? l2 : 0.2f * l2;
    l3 = l3 > 0.f ? l3 : 0.2f * l3;
    __half2 e01 = h2exp(__floats2half2_rn(l0, l1));
    __half2 e23 = h2exp(__floats2half2_rn(l2, l3));
    float4 rec;
    rec.x = __int_as_float(s);
    rec.y = __uint_as_float(*(const unsigned int*)&e01);
    rec.z = __uint_as_float(*(const unsigned int*)&e23);
    rec.w = 0.0f;
    return rec;
}

__global__ void edge_pass2(const int* __restrict__ e32, int N, int E) {
    int p = blockIdx.x * blockDim.x + threadIdx.x;
    int ET = E + N;
    int e0 = 2 * p, e1 = 2 * p + 1;
    if (e0 >= ET) return;
    bool has1 = (e1 < ET);
    int s0, d0, s1 = 0, d1 = 0;
    if (e1 < E) {
        if (g_is64) {
            int4 vs = *(const int4*)&e32[4 * p];
            int4 vd = *(const int4*)&e32[2 * E + 4 * p];
            s0 = vs.x; s1 = vs.z; d0 = vd.x; d1 = vd.z;
        } else {
            int2 vs = *(const int2*)&e32[2 * p];
            int2 vd = *(const int2*)&e32[E + 2 * p];
            s0 = vs.x; s1 = vs.y; d0 = vd.x; d1 = vd.y;
        }
    } else if (e0 >= E) {
        s0 = d0 = e0 - E;
        s1 = d1 = e1 - E;
    } else {
        if (e0 < E) {
            s0 = g_is64 ? e32[2 * e0] : e32[e0];
            d0 = g_is64 ? e32[2 * E + 2 * e0] : e32[E + e0];
        } else { s0 = d0 = e0 - E; }
        if (has1) {
            if (e1 < E) {
                s1 = g_is64 ? e32[2 * e1] : e32[e1];
                d1 = g_is64 ? e32[2 * E + 2 * e1] : e32[E + e1];
            } else { s1 = d1 = e1 - E; }
        }
    }
    float4 as0 = *(const float4*)&g_asrc[s0 * 4];
    float4 ad0 = *(const float4*)&g_adst[d0 * 4];
    float4 as1, ad1;
    if (has1) {
        as1 = *(const float4*)&g_asrc[s1 * 4];
        ad1 = *(const float4*)&g_adst[d1 * 4];
    }
    int2 rk = has1 ? *(const int2*)&g_rank[e0] : make_int2(g_rank[e0], 0);
    float4 rec0 = make_rec(s0, as0, ad0);
    g_pack[g_off[d0] + rk.x] = rec0;
    if (has1) {
        float4 rec1 = make_rec(s1, as1, ad1);
        g_pack[g_off[d1] + rk.y] = rec1;
    }
}

// ---------------- warp-per-dst-node aggregation; f32x2 packed FMA ----------------
__global__ void aggregate_kernel(const float* __restrict__ bias,
                                 float* __restrict__ out, int N) {
    int gw = (blockIdx.x * blockDim.x + threadIdx.x) >> 5;
    int lane = threadIdx.x & 31;
    if (gw >= N) return;
    int beg = g_off[gw], end = g_off[gw + 1];

    unsigned long long A0 = 0ull, A1 = 0ull, A2 = 0ull, A3 = 0ull;
    unsigned long long S01 = 0ull, S23 = 0ull;

    for (int j = beg; j < end; j++) {
        float4 rec = g_pack[j];
        int s = __float_as_int(rec.x);
        unsigned int u01 = __float_as_uint(rec.y);
        unsigned int u23 = __float_as_uint(rec.z);
        float2 w01 = __half22float2(*(const __half2*)&u01);
        float2 w23 = __half22float2(*(const __half2*)&u23);
        ADD2(S01, pk2(w01.x, w01.y));
        ADD2(S23, pk2(w23.x, w23.y));
        unsigned long long wA = pk2(w01.x, w01.x);
        unsigned long long wB = pk2(w01.y, w01.y);
        unsigned long long wC = pk2(w23.x, w23.x);
        unsigned long long wD = pk2(w23.y, w23.y);
        const __half2* xr = (const __half2*)(g_xh + s * HC);
        float2 v0 = __half22float2(xr[lane]);
        float2 v1 = __half22float2(xr[32 + lane]);
        float2 v2 = __half22float2(xr[64 + lane]);
        float2 v3 = __half22float2(xr[96 + lane]);
        FMA2(A0, wA, pk2(v0.x, v0.y));
        FMA2(A1, wB, pk2(v1.x, v1.y));
        FMA2(A2, wC, pk2(v2.x, v2.y));
        FMA2(A3, wD, pk2(v3.x, v3.y));
    }
    float a00, a01, a10, a11, a20, a21, a30, a31, s0, s1, s2, s3;
    upk2(A0, a00, a01); upk2(A1, a10, a11);
    upk2(A2, a20, a21); upk2(A3, a30, a31);
    upk2(S01, s0, s1);  upk2(S23, s2, s3);

    float n0 = 0.25f / (s0 + 1e-16f);
    float n1 = 0.25f / (s1 + 1e-16f);
    float n2 = 0.25f / (s2 + 1e-16f);
    float n3 = 0.25f / (s3 + 1e-16f);
    int c = 2 * lane;
    float o0 = a00 * n0 + a10 * n1 + a20 * n2 + a30 * n3 + bias[c];
    float o1 = a01 * n0 + a11 * n1 + a21 * n2 + a31 * n3 + bias[c + 1];
    *(float2*)&out[gw * 64 + c] = make_float2(o0, o1);
}

// ---------------- launch ----------------
extern "C" void kernel_launch(void* const* d_in, const int* in_sizes, int n_in,
                              void* d_out, int out_size) {
    const float* meta_x  = (const float*)d_in[0];
    const int*   edge32  = (const int*)d_in[1];
    const float* W       = (const float*)d_in[2];
    const float* att_src = (const float*)d_in[3];
    const float* att_dst = (const float*)d_in[4];
    const float* bias    = (const float*)d_in[5];
    float*       out     = (float*)d_out;

    int N  = in_sizes[0] / 64;
    int E  = in_sizes[1] / 2;
    int ET = E + N;
    int nb = (N + 1023) / 1024;
    int np = (ET + 1) / 2;
    int degBlocks  = (np + 511) / 512;
    int gemmBlocks = (N + 63) / 64;

    detect_init_wh_kernel<<<(N + 255) / 256, 256>>>(edge32, W, N);
    gemm_degree_kernel<<<degBlocks + gemmBlocks, 512>>>(meta_x, att_src, att_dst,
                                                        edge32, N, E, degBlocks, gemmBlocks);
    scan_lookback<<<nb, 1024>>>(N, ET, nb);
    edge_pass2<<<(np + 255) / 256, 256>>>(edge32, N, E);
    aggregate_kernel<<<(N * 32 + 255) / 256, 256>>>(bias, out, N);
}